// round 1
// baseline (speedup 1.0000x reference)
#include <cuda_runtime.h>

#define N_ENTITY 100000
#define N_RELS   500
#define DIM      128
#define NTRIP    250000
#define NBATCH   500000
#define BNEPS    1e-5f
#define OUT_ENT  (N_ENTITY*DIM)
#define OUT_TOT  (OUT_ENT + N_RELS*DIM)

// ---------------- scratch (static device globals; no allocation) ----------------
__device__ __align__(16) float g_P0[N_ENTITY*DIM];   // 51.2 MB
__device__ __align__(16) float g_P1[N_ENTITY*DIM];   // 51.2 MB
__device__ __align__(16) float g_Q [N_RELS*DIM];
__device__ __align__(16) float g_Gt [DIM*256];       // [k][jj] jj<128 -> G0, else G1
__device__ __align__(16) float g_Grt[DIM*DIM];       // [k][j]
__device__ float g_cntE[N_ENTITY];
__device__ float g_cntR[N_RELS];
__device__ float g_sumE [DIM];
__device__ float g_sumE2[DIM];
__device__ float g_varR [DIM];
__device__ __align__(16) float g_alpha0[DIM], g_alpha1[DIM], g_alphar[DIM];
__device__ __align__(16) float g_d[DIM];
__device__ float g_sumZ[DIM], g_sumZ2[DIM];
__device__ __align__(16) float g_ac[DIM], g_dc[DIM], g_wt[DIM];
__device__ float g_Sc;
__device__ float g_s0[N_ENTITY], g_s1[N_ENTITY], g_sq[N_RELS];
__device__ float g_ebs[N_ENTITY];
__device__ float g_ebrel[N_RELS];

// ---------------- float4 helpers ----------------
__device__ __forceinline__ float4 f4add(float4 a, float4 b){ return make_float4(a.x+b.x,a.y+b.y,a.z+b.z,a.w+b.w); }
__device__ __forceinline__ float4 f4sub(float4 a, float4 b){ return make_float4(a.x-b.x,a.y-b.y,a.z-b.z,a.w-b.w); }
__device__ __forceinline__ float4 f4mul(float4 a, float4 b){ return make_float4(a.x*b.x,a.y*b.y,a.z*b.z,a.w*b.w); }
__device__ __forceinline__ float4 f4scale(float s, float4 b){ return make_float4(s*b.x,s*b.y,s*b.z,s*b.w); }

__device__ __forceinline__ void red4(float* p, float4 v){
    asm volatile("red.global.add.v4.f32 [%0], {%1, %2, %3, %4};"
        :: "l"(p), "f"(v.x), "f"(v.y), "f"(v.z), "f"(v.w) : "memory");
}

// ---------------- kernels ----------------
__global__ void k_zero(float* out){
    int i0 = blockIdx.x*blockDim.x + threadIdx.x;
    int stride = gridDim.x*blockDim.x;
    for (int i = i0; i < OUT_TOT; i += stride){
        out[i] = 0.f;
        if (i < N_ENTITY){ g_cntE[i] = 0.f; g_ebs[i] = 0.f; }
        if (i < N_RELS)  { g_cntR[i] = 0.f; g_ebrel[i] = 0.f; }
        if (i < DIM){ g_sumE[i]=0.f; g_sumE2[i]=0.f; g_varR[i]=0.f; g_sumZ[i]=0.f; g_sumZ2[i]=0.f; }
    }
}

__global__ void k_count(const int* __restrict__ trip){
    int i = blockIdx.x*blockDim.x + threadIdx.x;
    if (i < NTRIP){
        int t0 = trip[3*i], t1 = trip[3*i+1], t2 = trip[3*i+2];
        atomicAdd(&g_cntE[t0], 1.f);
        atomicAdd(&g_cntE[t1], 1.f);
        atomicAdd(&g_cntR[t2], 1.f);
    }
}

// count-weighted Σ E and Σ E^2 per feature (== BN0 stats for cols 0..255)
__global__ void k_entstats(const float* __restrict__ E){
    int j = threadIdx.x;                 // 128
    int e0 = blockIdx.x*250, e1 = min(e0+250, N_ENTITY);
    float a1 = 0.f, a2 = 0.f;
    for (int e = e0; e < e1; e++){
        float c = g_cntE[e];
        if (c != 0.f){
            float v = E[e*DIM + j];
            a1 += c*v;
            a2 += c*v*v;
        }
    }
    atomicAdd(&g_sumE [j], a1);
    atomicAdd(&g_sumE2[j], a2);
}

__global__ void k_relstats(const float* __restrict__ R){
    int j = threadIdx.x;                 // 128
    float a = 0.f;
    for (int r = 0; r < N_RELS; r++){
        float v = R[r*DIM + j];
        a += g_cntR[r]*v*v;
    }
    g_varR[j] = a;
}

__global__ void k_bn0fin(const float* __restrict__ a_w, const float* __restrict__ a_b,
                         const float* __restrict__ bn0_g, const float* __restrict__ bn0_b){
    __shared__ float dsh[384];
    int j = threadIdx.x;                 // 128
    const float inv = 1.f/(float)NBATCH;
    float m  = g_sumE[j]*inv;
    float v  = g_sumE2[j]*inv - m*m;
    float rs = rsqrtf(v + BNEPS);
    float a0 = bn0_g[j]*rs,       d0 = bn0_b[j]       - m*a0;
    float a1 = bn0_g[128+j]*rs,   d1 = bn0_b[128+j]   - m*a1;
    float vr = g_varR[j]*(1.f/(float)NTRIP);          // mean of r-cols is exactly 0
    float ar = bn0_g[256+j]*rsqrtf(vr + BNEPS);
    float dr = bn0_b[256+j];
    g_alpha0[j]=a0; g_alpha1[j]=a1; g_alphar[j]=ar;
    dsh[j]=d0; dsh[128+j]=d1; dsh[256+j]=dr;
    __syncthreads();
    float acc = a_b[j];
    #pragma unroll 8
    for (int k = 0; k < 384; k++) acc += a_w[j*384 + k]*dsh[k];
    g_d[j] = acc;
}

__global__ void k_makeG(const float* __restrict__ a_w){
    int k  = blockIdx.x;                 // 128
    int jj = threadIdx.x;                // 256
    int j  = jj & 127;
    float al = (jj < 128) ? g_alpha0[k] : g_alpha1[k];
    int col  = (jj < 128) ? k : 128 + k;
    g_Gt[k*256 + jj] = a_w[j*384 + col]*al;
    if (jj < 128) g_Grt[k*128 + jj] = a_w[jj*384 + 256 + k]*g_alphar[k];
}

// P0/P1 = E * G^T.  Block: 128 entities x 128 cols (y=0 -> P0, y=1 -> P1).
__global__ void __launch_bounds__(256) k_pgemm(const float* __restrict__ E){
    __shared__ float As[128*32];
    __shared__ float Bs[32*128];
    int tid = threadIdx.x;
    int tx = tid & 15, ty = tid >> 4;
    int e0 = blockIdx.x*128;
    int jh = blockIdx.y;

    float acc[8][8];
    #pragma unroll
    for (int i = 0; i < 8; i++)
        #pragma unroll
        for (int r = 0; r < 8; r++) acc[i][r] = 0.f;

    for (int kt = 0; kt < 128; kt += 32){
        #pragma unroll
        for (int i = 0; i < 4; i++){
            int lin = tid + i*256;           // float4 index
            int m  = lin >> 3;
            int k4 = (lin & 7) << 2;
            float4 v = make_float4(0.f,0.f,0.f,0.f);
            if (e0 + m < N_ENTITY) v = *(const float4*)&E[(e0+m)*DIM + kt + k4];
            *(float4*)&As[m*32 + k4] = v;
        }
        #pragma unroll
        for (int i = 0; i < 4; i++){
            int lin = tid + i*256;
            int k  = lin >> 5;
            int j4 = (lin & 31) << 2;
            *(float4*)&Bs[k*128 + j4] = *(const float4*)&g_Gt[(kt+k)*256 + jh*128 + j4];
        }
        __syncthreads();
        #pragma unroll
        for (int k = 0; k < 32; k++){
            float b[8];
            *(float4*)&b[0] = *(const float4*)&Bs[k*128 + tx*8];
            *(float4*)&b[4] = *(const float4*)&Bs[k*128 + tx*8 + 4];
            float a[8];
            #pragma unroll
            for (int i = 0; i < 8; i++) a[i] = As[(ty*8 + i)*32 + k];
            #pragma unroll
            for (int i = 0; i < 8; i++)
                #pragma unroll
                for (int r = 0; r < 8; r++) acc[i][r] += a[i]*b[r];
        }
        __syncthreads();
    }
    float* P = jh ? g_P1 : g_P0;
    #pragma unroll
    for (int i = 0; i < 8; i++){
        int e = e0 + ty*8 + i;
        if (e < N_ENTITY){
            *(float4*)&P[e*DIM + tx*8]     = make_float4(acc[i][0],acc[i][1],acc[i][2],acc[i][3]);
            *(float4*)&P[e*DIM + tx*8 + 4] = make_float4(acc[i][4],acc[i][5],acc[i][6],acc[i][7]);
        }
    }
}

__global__ void k_qgemm(const float* __restrict__ R){
    __shared__ float Rs[128];
    int rho = blockIdx.x, j = threadIdx.x;
    Rs[j] = R[rho*DIM + j];
    __syncthreads();
    float acc = 0.f;
    #pragma unroll 8
    for (int k = 0; k < 128; k++) acc += Rs[k]*g_Grt[k*128 + j];
    g_Q[rho*DIM + j] = acc;
}

// pass D1: accumulate Σz and Σz^2 over all 2*NTRIP rows (warp per triplet)
__global__ void k_bn1stats(const int* __restrict__ trip){
    int lane = threadIdx.x & 31;
    int warp = (blockIdx.x*blockDim.x + threadIdx.x) >> 5;
    int nw   = (gridDim.x*blockDim.x) >> 5;
    float4 dd = ((const float4*)g_d)[lane];
    const float4* P04 = (const float4*)g_P0;
    const float4* P14 = (const float4*)g_P1;
    const float4* Q4  = (const float4*)g_Q;
    float4 s1v = make_float4(0.f,0.f,0.f,0.f);
    float4 s2v = make_float4(0.f,0.f,0.f,0.f);
    for (int i = warp; i < NTRIP; i += nw){
        int t0 = trip[3*i], t1 = trip[3*i+1], t2 = trip[3*i+2];
        float4 p00 = P04[t0*32 + lane];
        float4 p11 = P14[t1*32 + lane];
        float4 p01 = P04[t1*32 + lane];
        float4 p10 = P14[t0*32 + lane];
        float4 q   = Q4 [t2*32 + lane];
        float4 zf = f4add(f4add(p00, p11), f4add(q, dd));
        float4 zb = f4add(f4add(p01, p10), f4sub(dd, q));
        s1v = f4add(s1v, f4add(zf, zb));
        s2v = f4add(s2v, f4add(f4mul(zf,zf), f4mul(zb,zb)));
    }
    int j4 = lane*4;
    atomicAdd(&g_sumZ[j4+0], s1v.x); atomicAdd(&g_sumZ[j4+1], s1v.y);
    atomicAdd(&g_sumZ[j4+2], s1v.z); atomicAdd(&g_sumZ[j4+3], s1v.w);
    atomicAdd(&g_sumZ2[j4+0], s2v.x); atomicAdd(&g_sumZ2[j4+1], s2v.y);
    atomicAdd(&g_sumZ2[j4+2], s2v.z); atomicAdd(&g_sumZ2[j4+3], s2v.w);
}

__global__ void k_bn1fin(const float* __restrict__ a2_w, const float* __restrict__ a2_b,
                         const float* __restrict__ bn1_g, const float* __restrict__ bn1_b){
    __shared__ float red[128];
    int j = threadIdx.x;
    const float inv = 1.f/(float)NBATCH;
    float mz = g_sumZ[j]*inv;
    float vz = g_sumZ2[j]*inv - mz*mz;
    float ac = bn1_g[j]*rsqrtf(vz + BNEPS);
    float dc = bn1_b[j] - mz*ac;
    g_ac[j] = ac; g_dc[j] = dc;
    float w = a2_w[j]*ac;
    g_wt[j] = w;
    red[j] = w*g_d[j] + a2_w[j]*dc;
    __syncthreads();
    for (int s = 64; s > 0; s >>= 1){
        if (j < s) red[j] += red[j+s];
        __syncthreads();
    }
    if (j == 0) g_Sc = red[0] + a2_b[0];
}

// per-entity / per-rel attention-logit dot products
__global__ void k_sent(){
    int lane = threadIdx.x & 31;
    int warp = (blockIdx.x*blockDim.x + threadIdx.x) >> 5;
    int nw   = (gridDim.x*blockDim.x) >> 5;
    float4 w4 = ((const float4*)g_wt)[lane];
    const float4* P04 = (const float4*)g_P0;
    const float4* P14 = (const float4*)g_P1;
    const float4* Q4  = (const float4*)g_Q;
    for (int job = warp; job < N_ENTITY + N_RELS; job += nw){
        if (job < N_ENTITY){
            float4 p = P04[job*32 + lane];
            float4 q = P14[job*32 + lane];
            float d0 = p.x*w4.x + p.y*w4.y + p.z*w4.z + p.w*w4.w;
            float d1 = q.x*w4.x + q.y*w4.y + q.z*w4.z + q.w*w4.w;
            #pragma unroll
            for (int off = 16; off > 0; off >>= 1){
                d0 += __shfl_down_sync(0xffffffffu, d0, off);
                d1 += __shfl_down_sync(0xffffffffu, d1, off);
            }
            if (lane == 0){ g_s0[job] = d0; g_s1[job] = d1; }
        } else {
            int rho = job - N_ENTITY;
            float4 p = Q4[rho*32 + lane];
            float d0 = p.x*w4.x + p.y*w4.y + p.z*w4.z + p.w*w4.w;
            #pragma unroll
            for (int off = 16; off > 0; off >>= 1)
                d0 += __shfl_down_sync(0xffffffffu, d0, off);
            if (lane == 0) g_sq[rho] = d0;
        }
    }
}

// pass D2: compute e_b per row, scatter e_b*z into entity/rel accumulators
__global__ void k_scatter(const int* __restrict__ trip, float* __restrict__ out){
    int lane = threadIdx.x & 31;
    int warp = (blockIdx.x*blockDim.x + threadIdx.x) >> 5;
    int nw   = (gridDim.x*blockDim.x) >> 5;
    float4 dd = ((const float4*)g_d)[lane];
    float Sc = g_Sc;
    const float4* P04 = (const float4*)g_P0;
    const float4* P14 = (const float4*)g_P1;
    const float4* Q4  = (const float4*)g_Q;
    for (int i = warp; i < NTRIP; i += nw){
        int t0 = trip[3*i], t1 = trip[3*i+1], t2 = trip[3*i+2];
        float sqv = g_sq[t2];
        float sf = g_s0[t0] + g_s1[t1] + sqv + Sc;
        float sb = g_s0[t1] + g_s1[t0] - sqv + Sc;
        float ef = expf(sf >= 0.f ? -sf : -0.01f*sf);
        float eb = expf(sb >= 0.f ? -sb : -0.01f*sb);
        float4 p00 = P04[t0*32 + lane];
        float4 p11 = P14[t1*32 + lane];
        float4 p01 = P04[t1*32 + lane];
        float4 p10 = P14[t0*32 + lane];
        float4 q   = Q4 [t2*32 + lane];
        float4 zf = f4add(f4add(p00, p11), f4add(q, dd));
        float4 zb = f4add(f4add(p01, p10), f4sub(dd, q));
        float4 vf = f4scale(ef, zf);
        float4 vb = f4scale(eb, zb);
        red4(out + (size_t)t0*DIM + lane*4, vf);
        red4(out + (size_t)t1*DIM + lane*4, vb);
        red4(out + OUT_ENT + (size_t)t2*DIM + lane*4, vf);
        if (lane == 0){
            atomicAdd(&g_ebs[t0], ef);
            atomicAdd(&g_ebs[t1], eb);
            atomicAdd(&g_ebrel[t2], ef);
        }
    }
}

__global__ void k_fin_ent(float* __restrict__ out){
    float4* O = (float4*)out;
    int i0 = blockIdx.x*blockDim.x + threadIdx.x;
    int stride = gridDim.x*blockDim.x;
    for (int idx = i0; idx < N_ENTITY*32; idx += stride){
        int e = idx >> 5, l = idx & 31;
        float ebv = g_ebs[e];
        float den = (ebv == 0.f) ? 1e-12f : ebv;
        float inv = 1.f/den;
        float4 z = O[idx];
        float4 a = ((const float4*)g_ac)[l];
        float4 d = ((const float4*)g_dc)[l];
        z.x = (a.x*z.x + d.x*ebv)*inv;
        z.y = (a.y*z.y + d.y*ebv)*inv;
        z.z = (a.z*z.z + d.z*ebv)*inv;
        z.w = (a.w*z.w + d.w*ebv)*inv;
        O[idx] = z;
    }
}

__global__ void k_fin_rel(float* __restrict__ out){
    float4* O = (float4*)out + N_ENTITY*32;
    int i0 = blockIdx.x*blockDim.x + threadIdx.x;
    int stride = gridDim.x*blockDim.x;
    for (int idx = i0; idx < N_RELS*32; idx += stride){
        int r = idx >> 5, l = idx & 31;
        float ebv = g_ebrel[r];
        float inv = 1.f/fmaxf(g_cntR[r], 1.f);
        float4 z = O[idx];
        float4 a = ((const float4*)g_ac)[l];
        float4 d = ((const float4*)g_dc)[l];
        z.x = (a.x*z.x + d.x*ebv)*inv;
        z.y = (a.y*z.y + d.y*ebv)*inv;
        z.z = (a.z*z.z + d.z*ebv)*inv;
        z.w = (a.w*z.w + d.w*ebv)*inv;
        O[idx] = z;
    }
}

// ---------------- launcher ----------------
extern "C" void kernel_launch(void* const* d_in, const int* in_sizes, int n_in,
                              void* d_out, int out_size){
    const int*   trip  = (const int*)  d_in[0];
    const float* E     = (const float*)d_in[1];
    const float* R     = (const float*)d_in[2];
    const float* a_w   = (const float*)d_in[3];
    const float* a_b   = (const float*)d_in[4];
    const float* a2_w  = (const float*)d_in[5];
    const float* a2_b  = (const float*)d_in[6];
    const float* bn0_g = (const float*)d_in[7];
    const float* bn0_b = (const float*)d_in[8];
    const float* bn1_g = (const float*)d_in[9];
    const float* bn1_b = (const float*)d_in[10];
    float* out = (float*)d_out;

    k_zero<<<2048, 256>>>(out);
    k_count<<<(NTRIP + 255)/256, 256>>>(trip);
    k_entstats<<<400, 128>>>(E);
    k_relstats<<<1, 128>>>(R);
    k_bn0fin<<<1, 128>>>(a_w, a_b, bn0_g, bn0_b);
    k_makeG<<<128, 256>>>(a_w);
    k_pgemm<<<dim3(782, 2), 256>>>(E);
    k_qgemm<<<N_RELS, 128>>>(R);
    k_bn1stats<<<1024, 256>>>(trip);
    k_bn1fin<<<1, 128>>>(a2_w, a2_b, bn1_g, bn1_b);
    k_sent<<<1600, 256>>>();
    k_scatter<<<1024, 256>>>(trip, out);
    k_fin_ent<<<2048, 256>>>(out);
    k_fin_rel<<<63, 256>>>(out);
}

// round 2
// speedup vs baseline: 1.2535x; 1.2535x over previous
#include <cuda_runtime.h>

#define N_ENTITY 100000
#define N_RELS   500
#define DIM      128
#define NTRIP    250000
#define NBATCH   500000
#define BNEPS    1e-5f
#define OUT_ENT  (N_ENTITY*DIM)
#define OUT_TOT  (OUT_ENT + N_RELS*DIM)

typedef unsigned long long ull;

// ---------------- scratch (static device globals; no allocation) ----------------
__device__ __align__(16) float g_PI[N_ENTITY*256];   // interleaved P0|P1 per entity, 102.4 MB
__device__ __align__(16) float g_Q [N_RELS*DIM];
__device__ __align__(16) float g_Gt [DIM*256];       // [k][jj] jj<128 -> G0, else G1
__device__ __align__(16) float g_Grt[DIM*DIM];       // [k][j]
__device__ float g_cntE[N_ENTITY];
__device__ float g_cntR[N_RELS];
__device__ float g_sumE [DIM];
__device__ float g_sumE2[DIM];
__device__ float g_varR [DIM];
__device__ __align__(16) float g_alpha0[DIM], g_alpha1[DIM], g_alphar[DIM];
__device__ __align__(16) float g_d[DIM];
__device__ float g_sumZ2[DIM];
__device__ __align__(16) float g_ac[DIM], g_dc[DIM], g_wt[DIM];
__device__ __align__(16) float g_u0[DIM], g_u1[DIM];
__device__ float g_Sc;
__device__ float g_s0[N_ENTITY], g_s1[N_ENTITY], g_sq[N_RELS];
__device__ float g_ebs[N_ENTITY];
__device__ float g_ebrel[N_RELS];

// ---------------- float4 helpers ----------------
__device__ __forceinline__ float4 f4add(float4 a, float4 b){ return make_float4(a.x+b.x,a.y+b.y,a.z+b.z,a.w+b.w); }
__device__ __forceinline__ float4 f4sub(float4 a, float4 b){ return make_float4(a.x-b.x,a.y-b.y,a.z-b.z,a.w-b.w); }
__device__ __forceinline__ float4 f4mul(float4 a, float4 b){ return make_float4(a.x*b.x,a.y*b.y,a.z*b.z,a.w*b.w); }
__device__ __forceinline__ float4 f4scale(float s, float4 b){ return make_float4(s*b.x,s*b.y,s*b.z,s*b.w); }

__device__ __forceinline__ void red4(float* p, float4 v){
    asm volatile("red.global.add.v4.f32 [%0], {%1, %2, %3, %4};"
        :: "l"(p), "f"(v.x), "f"(v.y), "f"(v.z), "f"(v.w) : "memory");
}
__device__ __forceinline__ float4 ldg4(const float4* p){
    return __ldg(p);
}

// ---------------- kernels ----------------
__global__ void k_zero(float* out){
    int i0 = blockIdx.x*blockDim.x + threadIdx.x;
    int stride = gridDim.x*blockDim.x;
    for (int i = i0; i < OUT_TOT; i += stride){
        out[i] = 0.f;
        if (i < N_ENTITY){ g_cntE[i] = 0.f; g_ebs[i] = 0.f; }
        if (i < N_RELS)  { g_cntR[i] = 0.f; g_ebrel[i] = 0.f; }
        if (i < DIM){ g_sumE[i]=0.f; g_sumE2[i]=0.f; g_varR[i]=0.f; g_sumZ2[i]=0.f; }
    }
}

__global__ void k_count(const int* __restrict__ trip){
    int i = blockIdx.x*blockDim.x + threadIdx.x;
    if (i < NTRIP){
        int t0 = trip[3*i], t1 = trip[3*i+1], t2 = trip[3*i+2];
        atomicAdd(&g_cntE[t0], 1.f);
        atomicAdd(&g_cntE[t1], 1.f);
        atomicAdd(&g_cntR[t2], 1.f);
    }
}

// count-weighted Σ E and Σ E^2 per feature (== BN0 stats for cols 0..255)
__global__ void k_entstats(const float* __restrict__ E){
    int j = threadIdx.x;                 // 128
    int e0 = blockIdx.x*125, e1 = min(e0+125, N_ENTITY);
    float a1 = 0.f, a2 = 0.f;
    for (int e = e0; e < e1; e++){
        float c = g_cntE[e];
        if (c != 0.f){
            float v = E[e*DIM + j];
            a1 += c*v;
            a2 += c*v*v;
        }
    }
    atomicAdd(&g_sumE [j], a1);
    atomicAdd(&g_sumE2[j], a2);
}

__global__ void k_relstats(const float* __restrict__ R){
    int j = threadIdx.x;                 // 128
    int r0 = blockIdx.x*8, r1 = min(r0+8, N_RELS);
    float a = 0.f;
    for (int r = r0; r < r1; r++){
        float v = R[r*DIM + j];
        a += g_cntR[r]*v*v;
    }
    atomicAdd(&g_varR[j], a);
}

__global__ void k_bn0fin(const float* __restrict__ a_w, const float* __restrict__ a_b,
                         const float* __restrict__ bn0_g, const float* __restrict__ bn0_b){
    __shared__ float dsh[384];
    int j = threadIdx.x;                 // 128
    const float inv = 1.f/(float)NBATCH;
    float m  = g_sumE[j]*inv;
    float v  = g_sumE2[j]*inv - m*m;
    float rs = rsqrtf(v + BNEPS);
    float a0 = bn0_g[j]*rs,       d0 = bn0_b[j]       - m*a0;
    float a1 = bn0_g[128+j]*rs,   d1 = bn0_b[128+j]   - m*a1;
    float vr = g_varR[j]*(1.f/(float)NTRIP);          // mean of r-cols is exactly 0
    float ar = bn0_g[256+j]*rsqrtf(vr + BNEPS);
    float dr = bn0_b[256+j];
    g_alpha0[j]=a0; g_alpha1[j]=a1; g_alphar[j]=ar;
    dsh[j]=d0; dsh[128+j]=d1; dsh[256+j]=dr;
    __syncthreads();
    float acc = a_b[j];
    #pragma unroll 8
    for (int k = 0; k < 384; k++) acc += a_w[j*384 + k]*dsh[k];
    g_d[j] = acc;
}

__global__ void k_makeG(const float* __restrict__ a_w){
    int k  = blockIdx.x;                 // 128
    int jj = threadIdx.x;                // 256
    int j  = jj & 127;
    float al = (jj < 128) ? g_alpha0[k] : g_alpha1[k];
    int col  = (jj < 128) ? k : 128 + k;
    g_Gt[k*256 + jj] = a_w[j*384 + col]*al;
    if (jj < 128) g_Grt[k*128 + jj] = a_w[jj*384 + 256 + k]*g_alphar[k];
}

// P = E * G^T into interleaved layout.  Block: 128 entities x 128 cols
// (blockIdx.y=0 -> P0 half, =1 -> P1 half).  Inner loop uses packed f32x2 FMA.
__global__ void __launch_bounds__(256) k_pgemm(const float* __restrict__ E){
    __shared__ float As[128*32];
    __shared__ float Bs[32*128];
    int tid = threadIdx.x;
    int tx = tid & 15, ty = tid >> 4;
    int e0 = blockIdx.x*128;
    int jh = blockIdx.y;

    ull acc2[8][4];
    #pragma unroll
    for (int i = 0; i < 8; i++)
        #pragma unroll
        for (int r = 0; r < 4; r++) acc2[i][r] = 0ull;

    for (int kt = 0; kt < 128; kt += 32){
        #pragma unroll
        for (int i = 0; i < 4; i++){
            int lin = tid + i*256;           // float4 index
            int m  = lin >> 3;
            int k4 = (lin & 7) << 2;
            float4 v = make_float4(0.f,0.f,0.f,0.f);
            if (e0 + m < N_ENTITY) v = *(const float4*)&E[(e0+m)*DIM + kt + k4];
            *(float4*)&As[m*32 + k4] = v;
        }
        #pragma unroll
        for (int i = 0; i < 4; i++){
            int lin = tid + i*256;
            int k  = lin >> 5;
            int j4 = (lin & 31) << 2;
            *(float4*)&Bs[k*128 + j4] = *(const float4*)&g_Gt[(kt+k)*256 + jh*128 + j4];
        }
        __syncthreads();
        #pragma unroll
        for (int k = 0; k < 32; k++){
            // 4 packed b-pairs (8 consecutive floats, 2x LDS.128)
            double2 bl0 = *(const double2*)&Bs[k*128 + tx*8];
            double2 bl1 = *(const double2*)&Bs[k*128 + tx*8 + 4];
            ull b2[4];
            b2[0] = __double_as_longlong(bl0.x);
            b2[1] = __double_as_longlong(bl0.y);
            b2[2] = __double_as_longlong(bl1.x);
            b2[3] = __double_as_longlong(bl1.y);
            #pragma unroll
            for (int i = 0; i < 8; i++){
                unsigned ab = __float_as_uint(As[(ty*8 + i)*32 + k]);
                ull a2;
                asm("mov.b64 %0, {%1, %1};" : "=l"(a2) : "r"(ab));
                #pragma unroll
                for (int r = 0; r < 4; r++)
                    asm("fma.rn.f32x2 %0, %1, %2, %0;" : "+l"(acc2[i][r]) : "l"(a2), "l"(b2[r]));
            }
        }
        __syncthreads();
    }
    #pragma unroll
    for (int i = 0; i < 8; i++){
        int e = e0 + ty*8 + i;
        if (e < N_ENTITY){
            float4 v0, v1;
            v0.x = __uint_as_float((unsigned)(acc2[i][0]));
            v0.y = __uint_as_float((unsigned)(acc2[i][0] >> 32));
            v0.z = __uint_as_float((unsigned)(acc2[i][1]));
            v0.w = __uint_as_float((unsigned)(acc2[i][1] >> 32));
            v1.x = __uint_as_float((unsigned)(acc2[i][2]));
            v1.y = __uint_as_float((unsigned)(acc2[i][2] >> 32));
            v1.z = __uint_as_float((unsigned)(acc2[i][3]));
            v1.w = __uint_as_float((unsigned)(acc2[i][3] >> 32));
            *(float4*)&g_PI[e*256 + jh*128 + tx*8]     = v0;
            *(float4*)&g_PI[e*256 + jh*128 + tx*8 + 4] = v1;
        }
    }
}

__global__ void k_qgemm(const float* __restrict__ R){
    __shared__ float Rs[128];
    int rho = blockIdx.x, j = threadIdx.x;
    Rs[j] = R[rho*DIM + j];
    __syncthreads();
    float acc = 0.f;
    #pragma unroll 8
    for (int k = 0; k < 128; k++) acc += Rs[k]*g_Grt[k*128 + j];
    g_Q[rho*DIM + j] = acc;
}

// pass D1: accumulate Σz^2 over all 2*NTRIP rows (warp per triplet). Σz is analytic.
__global__ void k_bn1stats(const int* __restrict__ trip){
    int lane = threadIdx.x & 31;
    int warp = (blockIdx.x*blockDim.x + threadIdx.x) >> 5;
    int nw   = (gridDim.x*blockDim.x) >> 5;
    float4 dd = ((const float4*)g_d)[lane];
    const float4* PI4 = (const float4*)g_PI;
    const float4* Q4  = (const float4*)g_Q;
    float4 s2v = make_float4(0.f,0.f,0.f,0.f);
    for (int i = warp; i < NTRIP; i += nw){
        int t0 = trip[3*i], t1 = trip[3*i+1], t2 = trip[3*i+2];
        float4 p00 = ldg4(&PI4[t0*64 + lane]);
        float4 p10 = ldg4(&PI4[t0*64 + 32 + lane]);
        float4 p01 = ldg4(&PI4[t1*64 + lane]);
        float4 p11 = ldg4(&PI4[t1*64 + 32 + lane]);
        float4 q   = ldg4(&Q4 [t2*32 + lane]);
        float4 zf = f4add(f4add(p00, p11), f4add(q, dd));
        float4 zb = f4add(f4add(p01, p10), f4sub(dd, q));
        s2v = f4add(s2v, f4add(f4mul(zf,zf), f4mul(zb,zb)));
    }
    int j4 = lane*4;
    atomicAdd(&g_sumZ2[j4+0], s2v.x); atomicAdd(&g_sumZ2[j4+1], s2v.y);
    atomicAdd(&g_sumZ2[j4+2], s2v.z); atomicAdd(&g_sumZ2[j4+3], s2v.w);
}

__global__ void k_bn1fin(const float* __restrict__ a2_w, const float* __restrict__ a2_b,
                         const float* __restrict__ bn1_g, const float* __restrict__ bn1_b){
    __shared__ float wts[128];
    __shared__ float red[128];
    int j = threadIdx.x;
    // analytic Σz over the 2*NTRIP batch: Q terms cancel between fwd/bwd rows
    float sz = 0.f;
    #pragma unroll 4
    for (int k = 0; k < 128; k++){
        float se = g_sumE[k];
        sz += se*(g_Gt[k*256 + j] + g_Gt[k*256 + 128 + j]);
    }
    float dj = g_d[j];
    sz += 2.f*(float)NTRIP*dj;
    const float inv = 1.f/(float)NBATCH;
    float mz = sz*inv;
    float vz = g_sumZ2[j]*inv - mz*mz;
    float ac = bn1_g[j]*rsqrtf(vz + BNEPS);
    float dc = bn1_b[j] - mz*ac;
    g_ac[j] = ac; g_dc[j] = dc;
    float w = a2_w[j]*ac;
    g_wt[j] = w;
    wts[j] = w;
    red[j] = w*dj + a2_w[j]*dc;
    __syncthreads();
    // u-vectors: u0 = G0^T wt, u1 = G1^T wt   (thread j plays the role of k)
    float u0 = 0.f, u1 = 0.f;
    #pragma unroll 4
    for (int jj = 0; jj < 128; jj++){
        float wv = wts[jj];
        u0 += wv*g_Gt[j*256 + jj];
        u1 += wv*g_Gt[j*256 + 128 + jj];
    }
    g_u0[j] = u0; g_u1[j] = u1;
    for (int s = 64; s > 0; s >>= 1){
        if (j < s) red[j] += red[j+s];
        __syncthreads();
    }
    if (j == 0) g_Sc = red[0] + a2_b[0];
}

// s0[e] = E[e]·u0, s1[e] = E[e]·u1  — one 51MB pass over E instead of 102MB over P
__global__ void k_sents(const float* __restrict__ E){
    int lane = threadIdx.x & 31;
    int warp = (blockIdx.x*blockDim.x + threadIdx.x) >> 5;
    int nw   = (gridDim.x*blockDim.x) >> 5;
    float4 u04 = ((const float4*)g_u0)[lane];
    float4 u14 = ((const float4*)g_u1)[lane];
    const float4* E4 = (const float4*)E;
    for (int e = warp; e < N_ENTITY; e += nw){
        float4 v = ldg4(&E4[e*32 + lane]);
        float d0 = v.x*u04.x + v.y*u04.y + v.z*u04.z + v.w*u04.w;
        float d1 = v.x*u14.x + v.y*u14.y + v.z*u14.z + v.w*u14.w;
        #pragma unroll
        for (int off = 16; off > 0; off >>= 1){
            d0 += __shfl_down_sync(0xffffffffu, d0, off);
            d1 += __shfl_down_sync(0xffffffffu, d1, off);
        }
        if (lane == 0){ g_s0[e] = d0; g_s1[e] = d1; }
    }
}

__global__ void k_sq(){
    int lane = threadIdx.x & 31;
    int warp = (blockIdx.x*blockDim.x + threadIdx.x) >> 5;
    if (warp >= N_RELS) return;
    float4 w4 = ((const float4*)g_wt)[lane];
    float4 p  = ((const float4*)g_Q)[warp*32 + lane];
    float d0 = p.x*w4.x + p.y*w4.y + p.z*w4.z + p.w*w4.w;
    #pragma unroll
    for (int off = 16; off > 0; off >>= 1)
        d0 += __shfl_down_sync(0xffffffffu, d0, off);
    if (lane == 0) g_sq[warp] = d0;
}

// pass D2: compute e_b per row, scatter e_b*z into entity/rel accumulators
__global__ void k_scatter(const int* __restrict__ trip, float* __restrict__ out){
    int lane = threadIdx.x & 31;
    int warp = (blockIdx.x*blockDim.x + threadIdx.x) >> 5;
    int nw   = (gridDim.x*blockDim.x) >> 5;
    float4 dd = ((const float4*)g_d)[lane];
    float Sc = g_Sc;
    const float4* PI4 = (const float4*)g_PI;
    const float4* Q4  = (const float4*)g_Q;
    for (int i = warp; i < NTRIP; i += nw){
        int t0 = trip[3*i], t1 = trip[3*i+1], t2 = trip[3*i+2];
        float sqv = __ldg(&g_sq[t2]);
        float s0a = __ldg(&g_s0[t0]), s0b = __ldg(&g_s0[t1]);
        float s1a = __ldg(&g_s1[t0]), s1b = __ldg(&g_s1[t1]);
        float sf = s0a + s1b + sqv + Sc;
        float sb = s0b + s1a - sqv + Sc;
        float ef = expf(sf >= 0.f ? -sf : -0.01f*sf);
        float eb = expf(sb >= 0.f ? -sb : -0.01f*sb);
        float4 p00 = ldg4(&PI4[t0*64 + lane]);
        float4 p10 = ldg4(&PI4[t0*64 + 32 + lane]);
        float4 p01 = ldg4(&PI4[t1*64 + lane]);
        float4 p11 = ldg4(&PI4[t1*64 + 32 + lane]);
        float4 q   = ldg4(&Q4 [t2*32 + lane]);
        float4 zf = f4add(f4add(p00, p11), f4add(q, dd));
        float4 zb = f4add(f4add(p01, p10), f4sub(dd, q));
        float4 vf = f4scale(ef, zf);
        float4 vb = f4scale(eb, zb);
        red4(out + (size_t)t0*DIM + lane*4, vf);
        red4(out + (size_t)t1*DIM + lane*4, vb);
        red4(out + OUT_ENT + (size_t)t2*DIM + lane*4, vf);
        if (lane == 0){
            atomicAdd(&g_ebs[t0], ef);
            atomicAdd(&g_ebs[t1], eb);
            atomicAdd(&g_ebrel[t2], ef);
        }
    }
}

__global__ void k_fin_ent(float* __restrict__ out){
    float4* O = (float4*)out;
    int i0 = blockIdx.x*blockDim.x + threadIdx.x;
    int stride = gridDim.x*blockDim.x;
    for (int idx = i0; idx < N_ENTITY*32; idx += stride){
        int e = idx >> 5, l = idx & 31;
        float ebv = g_ebs[e];
        float den = (ebv == 0.f) ? 1e-12f : ebv;
        float inv = 1.f/den;
        float4 z = O[idx];
        float4 a = ((const float4*)g_ac)[l];
        float4 d = ((const float4*)g_dc)[l];
        z.x = (a.x*z.x + d.x*ebv)*inv;
        z.y = (a.y*z.y + d.y*ebv)*inv;
        z.z = (a.z*z.z + d.z*ebv)*inv;
        z.w = (a.w*z.w + d.w*ebv)*inv;
        O[idx] = z;
    }
}

__global__ void k_fin_rel(float* __restrict__ out){
    float4* O = (float4*)out + N_ENTITY*32;
    int i0 = blockIdx.x*blockDim.x + threadIdx.x;
    int stride = gridDim.x*blockDim.x;
    for (int idx = i0; idx < N_RELS*32; idx += stride){
        int r = idx >> 5, l = idx & 31;
        float ebv = g_ebrel[r];
        float inv = 1.f/fmaxf(g_cntR[r], 1.f);
        float4 z = O[idx];
        float4 a = ((const float4*)g_ac)[l];
        float4 d = ((const float4*)g_dc)[l];
        z.x = (a.x*z.x + d.x*ebv)*inv;
        z.y = (a.y*z.y + d.y*ebv)*inv;
        z.z = (a.z*z.z + d.z*ebv)*inv;
        z.w = (a.w*z.w + d.w*ebv)*inv;
        O[idx] = z;
    }
}

// ---------------- launcher ----------------
extern "C" void kernel_launch(void* const* d_in, const int* in_sizes, int n_in,
                              void* d_out, int out_size){
    const int*   trip  = (const int*)  d_in[0];
    const float* E     = (const float*)d_in[1];
    const float* R     = (const float*)d_in[2];
    const float* a_w   = (const float*)d_in[3];
    const float* a_b   = (const float*)d_in[4];
    const float* a2_w  = (const float*)d_in[5];
    const float* a2_b  = (const float*)d_in[6];
    const float* bn0_g = (const float*)d_in[7];
    const float* bn0_b = (const float*)d_in[8];
    const float* bn1_g = (const float*)d_in[9];
    const float* bn1_b = (const float*)d_in[10];
    float* out = (float*)d_out;

    k_zero<<<2048, 256>>>(out);
    k_count<<<(NTRIP + 255)/256, 256>>>(trip);
    k_entstats<<<800, 128>>>(E);
    k_relstats<<<63, 128>>>(R);
    k_bn0fin<<<1, 128>>>(a_w, a_b, bn0_g, bn0_b);
    k_makeG<<<128, 256>>>(a_w);
    k_pgemm<<<dim3(782, 2), 256>>>(E);
    k_qgemm<<<N_RELS, 128>>>(R);
    k_bn1stats<<<1024, 256>>>(trip);
    k_bn1fin<<<1, 128>>>(a2_w, a2_b, bn1_g, bn1_b);
    k_sents<<<800, 256>>>(E);
    k_sq<<<63, 256>>>();
    k_scatter<<<1024, 256>>>(trip, out);
    k_fin_ent<<<2048, 256>>>(out);
    k_fin_rel<<<63, 256>>>(out);
}